// round 6
// baseline (speedup 1.0000x reference)
#include <cuda_runtime.h>
#include <cstdint>

// ============================================================================
// ConvLSTMEncoder == 3-layer LSTM (K=3 conv over length-1 dim -> center tap).
//   B=256, T=512, CIN=64, H=128.  gates[b,4H] = [in; h] @ Wc^T + bias
// Round-5: skewed layer pipeline (1 cross-CTA barrier / macro-step) +
//   512 threads (4 warps/SMSP) for latency hiding.
//   16 warps = 2 batch-halves x 2 row-groups x 4 k-quarters.
//   Lane tile = 4 rows x 2 batches; z stride 18 (even) -> z pair = 1 LDS.64.
//   Per warp-k: LDS.128(w) + LDS.64(z) + 2 DUP + 4 FMA2  (8 instr / 4 fma2)
//   -> per-SMSP/macro: issue 5632 = fma-pipe 5632 (floor), LSU 2816.
// 128 CTAs = 16 batch-groups x 8 gate-slices; weights fp32 in SMEM;
// h exchange via L2 __device__ buffer + monotonic counter barrier.
// ============================================================================

#define T_STEPS 512

// smem float offsets:
#define WOFF_L0 0
#define WOFF_L1 12288
#define WOFF_L2 28672
#define ZD_OFF  45056                  // z: [448][18] floats (8064)
#define GB_OFF  53120                  // gbuf: [4][16][66] floats (4224)
#define SMEM_FLOATS 57344
#define SMEM_BYTES  (SMEM_FLOATS * 4)  // 229376

__device__ float    g_hbuf[3 * 2 * 128 * 256];  // [layer][parity][unit][batch]
__device__ unsigned g_ctr[16];                  // per-group barrier counters

__global__ void reset_ctr_kernel() {
    if (threadIdx.x < 16) g_ctr[threadIdx.x] = 0u;
}

__device__ __forceinline__ float fast_rcp(float x) {
    float r; asm("rcp.approx.f32 %0, %1;" : "=f"(r) : "f"(x)); return r;
}
__device__ __forceinline__ float sigm(float x) {
    return fast_rcp(1.0f + __expf(-x));
}
__device__ __forceinline__ float tanh_f(float x) {
    x = fminf(fmaxf(x, -15.0f), 15.0f);
    float e = __expf(-2.0f * x);
    return (1.0f - e) * fast_rcp(1.0f + e);
}

#define FMA2(acc, a, b) asm("fma.rn.f32x2 %0, %1, %2, %0;" : "+l"(acc) : "l"(a), "l"(b))
#define DUP2(d, s)      asm("mov.b64 %0, {%1, %1};" : "=l"(d) : "r"(__float_as_uint(s)))

// Barrier among the 8 CTAs of one batch-group. __syncthreads orders all
// threads' prior stores before tid0's cumulative gpu-scope fence + atomic.
__device__ __forceinline__ void group_barrier(int grp, unsigned target) {
    __syncthreads();
    if (threadIdx.x == 0) {
        __threadfence();
        atomicAdd(&g_ctr[grp], 1u);
        unsigned v;
        for (;;) {
            asm volatile("ld.global.acquire.gpu.u32 %0, [%1];"
                         : "=r"(v) : "l"(&g_ctr[grp]) : "memory");
            if (v >= target) break;
            __nanosleep(20);
        }
    }
    __syncthreads();
}

// GEMV tile: KD/4 k-iters, 4 rows x 2 batches per lane.
template<int KD>
__device__ __forceinline__ void gemv_store(
    const float* __restrict__ Wcol,   // Wsm + Loff + kq*(KD/4)*64 + wro
    const float* __restrict__ zcol,   // zd + (zoff + kq*(KD/4))*18 + b0
    float* __restrict__ gdst)         // gbuf + kq*1056 + b0*66 + wro
{
    unsigned long long a0 = 0, a1 = 0, a2 = 0, a3 = 0;
#pragma unroll 8
    for (int k = 0; k < KD / 4; k++) {
        ulonglong2 w = *(const ulonglong2*)(Wcol + k * 64);  // rows r0..r0+3
        float2 z2 = *(const float2*)(zcol + k * 18);         // batches b0, b0+1
        unsigned long long zz0, zz1;
        DUP2(zz0, z2.x); DUP2(zz1, z2.y);
        FMA2(a0, w.x, zz0); FMA2(a1, w.y, zz0);
        FMA2(a2, w.x, zz1); FMA2(a3, w.y, zz1);
    }
    *(unsigned long long*)(gdst + 0)      = a0;   // [b0][r0..r0+1]
    *(unsigned long long*)(gdst + 2)      = a1;   // [b0][r0+2..r0+3]
    *(unsigned long long*)(gdst + 66)     = a2;   // [b0+1][r0..r0+1]
    *(unsigned long long*)(gdst + 68)     = a3;   // [b0+1][r0+2..r0+3]
}

__global__ void __launch_bounds__(512, 1) convlstm_kernel(
    const float* __restrict__ x,
    const float* __restrict__ W1, const float* __restrict__ b1,
    const float* __restrict__ W2, const float* __restrict__ b2,
    const float* __restrict__ W3, const float* __restrict__ b3,
    const float* __restrict__ h1i, const float* __restrict__ c1i,
    const float* __restrict__ h2i, const float* __restrict__ c2i,
    const float* __restrict__ h3i, const float* __restrict__ c3i,
    float* __restrict__ out)
{
    extern __shared__ float sm[];
    float* Wsm  = sm;
    float* zd   = sm + ZD_OFF;
    float* gbuf = sm + GB_OFF;

    const int tid = threadIdx.x;
    const int gid = blockIdx.x & 7;    // gate-slice: hidden units [16*gid, +16)
    const int bg  = blockIdx.x >> 3;   // batch group: batches [16*bg, +16)
    const int bgb = bg << 4;

    // ---- Prologue: weight slices (center tap), [k][row64] per layer ----
    for (int idx = tid; idx < 192 * 64; idx += 512) {
        int k = idx >> 6, r = idx & 63;
        int grow = ((r >> 4) << 7) | (gid << 4) | (r & 15);  // gate*128 + gid*16 + u
        Wsm[WOFF_L0 + idx] = W1[(size_t)grow * 576 + k * 3 + 1];
    }
    for (int idx = tid; idx < 256 * 64; idx += 512) {
        int k = idx >> 6, r = idx & 63;
        int grow = ((r >> 4) << 7) | (gid << 4) | (r & 15);
        Wsm[WOFF_L1 + idx] = W2[(size_t)grow * 768 + k * 3 + 1];
        Wsm[WOFF_L2 + idx] = W3[(size_t)grow * 768 + k * 3 + 1];
    }

    // ---- per-thread (u,b) registers: bias + c state (owners: tid<256) ----
    const int u = (tid >> 4) & 15, b = tid & 15;   // tid>=256 aliases (harmless)
    const int gub = (gid << 4) | u;
    float4 bL0 = make_float4(__ldg(&b1[gub]), __ldg(&b1[128 + gub]),
                             __ldg(&b1[256 + gub]), __ldg(&b1[384 + gub]));
    float4 bL1 = make_float4(__ldg(&b2[gub]), __ldg(&b2[128 + gub]),
                             __ldg(&b2[256 + gub]), __ldg(&b2[384 + gub]));
    float4 bL2 = make_float4(__ldg(&b3[gub]), __ldg(&b3[128 + gub]),
                             __ldg(&b3[256 + gub]), __ldg(&b3[384 + gub]));
    const int sidx = (bgb + b) * 128 + gub;
    float c0r = __ldg(&c1i[sidx]);
    float c1r = __ldg(&c2i[sidx]);
    float c2r = __ldg(&c3i[sidx]);

    // ---- publish initial h into both parities ----
    if (tid < 256) {
        float h0 = __ldg(&h1i[sidx]), h1v = __ldg(&h2i[sidx]), h2v = __ldg(&h3i[sidx]);
        int hb = gub * 256 + bgb + b;
#pragma unroll
        for (int par = 0; par < 2; par++) {
            g_hbuf[(0 * 2 + par) * 32768 + hb] = h0;
            g_hbuf[(1 * 2 + par) * 32768 + hb] = h1v;
            g_hbuf[(2 * 2 + par) * 32768 + hb] = h2v;
        }
    }
    unsigned target = 8;
    group_barrier(bg, target); target += 8;

    // GEMV warp/lane geometry: 16 warps = 2 bs x 2 rg x 4 kq
    const int warp = tid >> 5, lane = tid & 31;
    const int kq = warp & 3;             // k-quarter
    const int rg = (warp >> 2) & 1;      // row-group (32 rows)
    const int bs = warp >> 3;            // batch-half (8 batches)
    const int oct = lane & 7;            // 4-row octet within group
    const int pr  = lane >> 3;           // batch-pair within half
    const int wro = rg * 32 + oct * 4;   // row offset 0..60
    const int b0  = bs * 8 + pr * 2;     // even batch index
    float* gdst = gbuf + kq * 1056 + b0 * 66 + wro;

    // ======================= macro-step pipeline =======================
    for (int s = 0; s < T_STEPS + 2; s++) {
        const int pc = s & 1, pp = pc ^ 1;

        // ---- assemble z = [x(s) | h0 | h1 | h2] (448 rows x 16b, stride 18) ----
        if (s < T_STEPS) {
            const float* xb = x + (size_t)bgb * (T_STEPS * 64) + (size_t)s * 64;
#pragma unroll
            for (int i = 0; i < 2; i++) {
                int idx = tid + (i << 9);
                int bb = idx >> 6, k = idx & 63;
                zd[k * 18 + bb] = __ldg(&xb[(size_t)bb * (T_STEPS * 64) + k]);
            }
        }
#pragma unroll
        for (int Lh = 0; Lh < 3; Lh++) {
            const float* src = &g_hbuf[(Lh * 2 + pp) * 32768 + bgb];
            int unit = tid >> 2, b4 = (tid & 3) << 2;
            float4 v = __ldcg((const float4*)&src[unit * 256 + b4]);
            float* d = &zd[(64 + (Lh << 7) + unit) * 18 + b4];
            d[0] = v.x; d[1] = v.y; d[2] = v.z; d[3] = v.w;
        }
        __syncthreads();

        // -------- L0: t = s  (z rows 0..191) --------
        if (s < T_STEPS) {
            gemv_store<192>(Wsm + WOFF_L0 + kq * 48 * 64 + wro,
                            zd + (kq * 48) * 18 + b0, gdst);
        }
        __syncthreads();
        if (s < T_STEPS && tid < 256) {
            float gi = bL0.x, gf = bL0.y, go = bL0.z, gg = bL0.w;
#pragma unroll
            for (int q = 0; q < 4; q++) {
                const float* gb = gbuf + q * 1056 + b * 66;
                gi += gb[u]; gf += gb[16 + u]; go += gb[32 + u]; gg += gb[48 + u];
            }
            float cn = sigm(gf) * c0r + sigm(gi) * tanh_f(gg);
            float hn = sigm(go) * tanh_f(cn);
            c0r = cn;
            g_hbuf[(0 * 2 + pc) * 32768 + gub * 256 + bgb + b] = hn;
        }
        __syncthreads();

        // -------- L1: t = s-1  (z rows 64..319) --------
        if (s >= 1 && s <= T_STEPS) {
            gemv_store<256>(Wsm + WOFF_L1 + kq * 64 * 64 + wro,
                            zd + (64 + kq * 64) * 18 + b0, gdst);
        }
        __syncthreads();
        if (s >= 1 && s <= T_STEPS && tid < 256) {
            float gi = bL1.x, gf = bL1.y, go = bL1.z, gg = bL1.w;
#pragma unroll
            for (int q = 0; q < 4; q++) {
                const float* gb = gbuf + q * 1056 + b * 66;
                gi += gb[u]; gf += gb[16 + u]; go += gb[32 + u]; gg += gb[48 + u];
            }
            float cn = sigm(gf) * c1r + sigm(gi) * tanh_f(gg);
            float hn = sigm(go) * tanh_f(cn);
            c1r = cn;
            g_hbuf[(1 * 2 + pc) * 32768 + gub * 256 + bgb + b] = hn;
        }
        __syncthreads();

        // -------- L2: t = s-2  (z rows 192..447) --------
        if (s >= 2) {
            gemv_store<256>(Wsm + WOFF_L2 + kq * 64 * 64 + wro,
                            zd + (192 + kq * 64) * 18 + b0, gdst);
        }
        __syncthreads();
        if (s >= 2 && tid < 256) {
            float gi = bL2.x, gf = bL2.y, go = bL2.z, gg = bL2.w;
#pragma unroll
            for (int q = 0; q < 4; q++) {
                const float* gb = gbuf + q * 1056 + b * 66;
                gi += gb[u]; gf += gb[16 + u]; go += gb[32 + u]; gg += gb[48 + u];
            }
            float cn = sigm(gf) * c2r + sigm(gi) * tanh_f(gg);
            float hn = sigm(go) * tanh_f(cn);
            c2r = cn;
            g_hbuf[(2 * 2 + pc) * 32768 + gub * 256 + bgb + b] = hn;
            if (s == T_STEPS + 1)
                out[(size_t)(bgb + b) * 128 + gub] = hn;
        }

        group_barrier(bg, target); target += 8;
    }
}

extern "C" void kernel_launch(void* const* d_in, const int* in_sizes, int n_in,
                              void* d_out, int out_size) {
    (void)in_sizes; (void)n_in; (void)out_size;
    const float* x  = (const float*)d_in[0];
    const float* W1 = (const float*)d_in[1];
    const float* b1 = (const float*)d_in[2];
    const float* W2 = (const float*)d_in[3];
    const float* b2 = (const float*)d_in[4];
    const float* W3 = (const float*)d_in[5];
    const float* b3 = (const float*)d_in[6];
    const float* h1 = (const float*)d_in[7];
    const float* c1 = (const float*)d_in[8];
    const float* h2 = (const float*)d_in[9];
    const float* c2 = (const float*)d_in[10];
    const float* h3 = (const float*)d_in[11];
    const float* c3 = (const float*)d_in[12];
    float* out = (float*)d_out;

    cudaFuncSetAttribute(convlstm_kernel,
                         cudaFuncAttributeMaxDynamicSharedMemorySize, SMEM_BYTES);
    reset_ctr_kernel<<<1, 32>>>();
    convlstm_kernel<<<128, 512, SMEM_BYTES>>>(x, W1, b1, W2, b2, W3, b3,
                                              h1, c1, h2, c2, h3, c3, out);
}

// round 9
// speedup vs baseline: 1.1345x; 1.1345x over previous
#include <cuda_runtime.h>
#include <cstdint>

// ============================================================================
// ConvLSTMEncoder == 3-layer LSTM (K=3 conv over length-1 dim -> center tap).
//   B=256, T=512, CIN=64, H=128.  gates[b,4H] = [in; h] @ Wc^T + bias
// Round-8: minimal-serialization macro-step (R6 structure), BOTH bugs fixed:
//   - z layout: plain floats, stride 20 (R6 had overlapping stride-10 u64s)
//   - geometry: 2-way k-split -> complete (row,batch,kh) coverage with 256
//     lanes (R7's 4-way split silently dropped batches 4-7 and 12-15)
// Macro s computes L0(t=s), L1(t=s-1), L2(t=s-2) (independent):
//   assemble z -> BAR -> all 3 GEMVs (sync-free) -> BAR -> all 3 cells ->
//   cross-CTA group barrier.  (3 sync points per macro.)
// GEMV: 256 thr, 8 warps = 4 row-groups(16 rows) x 2 batch-halves(8 b).
//   Lane = kh(lane>>4) x oct((lane>>2)&3: 4-row quad) x pr(lane&3: 2-batch
//   pair).  k-halves reduced IN-LANE via shfl.bfly(16) + add.rn.f32x2 ->
//   single gbuf copy.  Per k: LDS.128(w) + LDS.64(z) + 2 DUP2 + 4 FMA2
//   = 8 issue slots / 8 fma-cycles (floor 5632 cyc/SMSP/macro).
//   W halves padded by 16 floats -> the two kh halves hit disjoint banks.
// 128 CTAs = 16 batch-groups x 8 gate-slices; weights fp32 in SMEM;
// h exchange via L2 __device__ buffer + monotonic counter barrier.
// ============================================================================

#define T_STEPS 512

// smem float offsets (half stride = (KD/2)*64 + 16):
#define WOFF_L0 0            // KD=192: 2 * 6160 = 12320
#define WOFF_L1 12320        // KD=256: 2 * 8208 = 16416
#define WOFF_L2 28736        // KD=256: 16416
#define ZD_OFF  45152        // z: [448][20] floats = 8960
#define GB_OFF  54112        // gbuf: [3][16][66] floats = 3168
#define SMEM_FLOATS 57280
#define SMEM_BYTES  (SMEM_FLOATS * 4)   // 229120

__device__ float    g_hbuf[3 * 2 * 128 * 256];  // [layer][parity][unit][batch]
__device__ unsigned g_ctr[16];                  // per-group barrier counters

__global__ void reset_ctr_kernel() {
    if (threadIdx.x < 16) g_ctr[threadIdx.x] = 0u;
}

__device__ __forceinline__ float fast_rcp(float x) {
    float r; asm("rcp.approx.f32 %0, %1;" : "=f"(r) : "f"(x)); return r;
}
__device__ __forceinline__ float sigm(float x) {
    return fast_rcp(1.0f + __expf(-x));
}
__device__ __forceinline__ float tanh_f(float x) {
    x = fminf(fmaxf(x, -15.0f), 15.0f);
    float e = __expf(-2.0f * x);
    return (1.0f - e) * fast_rcp(1.0f + e);
}

#define FMA2(acc, a, b) asm("fma.rn.f32x2 %0, %1, %2, %0;" : "+l"(acc) : "l"(a), "l"(b))
#define DUP2(d, s)      asm("mov.b64 %0, {%1, %1};" : "=l"(d) : "r"(__float_as_uint(s)))

// butterfly reduce of an f32x2 pair across the two k-halves (lane bit 4)
__device__ __forceinline__ unsigned long long bfly16_add2(unsigned long long a) {
    unsigned lo = (unsigned)a, hi = (unsigned)(a >> 32);
    unsigned plo = __shfl_xor_sync(0xffffffffu, lo, 16);
    unsigned phi = __shfl_xor_sync(0xffffffffu, hi, 16);
    unsigned long long p = ((unsigned long long)phi << 32) | plo;
    unsigned long long r;
    asm("add.rn.f32x2 %0, %1, %2;" : "=l"(r) : "l"(a), "l"(p));
    return r;
}

// Barrier among the 8 CTAs of one batch-group (monotonic counter in L2).
__device__ __forceinline__ void group_barrier(int grp, unsigned target) {
    __syncthreads();
    if (threadIdx.x == 0) {
        __threadfence();
        atomicAdd(&g_ctr[grp], 1u);
        unsigned v;
        for (;;) {
            asm volatile("ld.global.acquire.gpu.u32 %0, [%1];"
                         : "=r"(v) : "l"(&g_ctr[grp]) : "memory");
            if (v >= target) break;
            __nanosleep(20);
        }
    }
    __syncthreads();
}

// GEMV for one layer: lane handles 4 rows x 2 batches over its k-half,
// reduces the 2 halves via shfl.bfly(16); kh==0 lanes store complete sums.
template<int KD>
__device__ __forceinline__ void gemv_layer(
    const float* __restrict__ Wbase,   // Wsm + layer offset
    const float* __restrict__ zbase,   // zdf + zrow0*20
    int kh, int r0, int b0, float* __restrict__ gdst)
{
    constexpr int Q  = KD / 2;
    constexpr int QS = Q * 64 + 16;    // half stride incl. bank pad
    const float* Wcol = Wbase + kh * QS + r0;
    const float* zcol = zbase + kh * (Q * 20) + b0;
    unsigned long long a0 = 0, a1 = 0, a2 = 0, a3 = 0;
#pragma unroll 8
    for (int k = 0; k < Q; k++) {
        ulonglong2 w = *(const ulonglong2*)(Wcol + k * 64);  // rows r0..r0+3
        float2 z2 = *(const float2*)(zcol + k * 20);         // batches b0,b0+1
        unsigned long long zz0, zz1;
        DUP2(zz0, z2.x); DUP2(zz1, z2.y);
        FMA2(a0, w.x, zz0); FMA2(a1, w.y, zz0);
        FMA2(a2, w.x, zz1); FMA2(a3, w.y, zz1);
    }
    a0 = bfly16_add2(a0);
    a1 = bfly16_add2(a1);
    a2 = bfly16_add2(a2);
    a3 = bfly16_add2(a3);
    if (kh == 0) {
        *(unsigned long long*)(gdst + b0 * 66 + r0)          = a0;  // [b0][r0..+1]
        *(unsigned long long*)(gdst + b0 * 66 + r0 + 2)      = a1;  // [b0][r0+2..+3]
        *(unsigned long long*)(gdst + b0 * 66 + 66 + r0)     = a2;
        *(unsigned long long*)(gdst + b0 * 66 + 66 + r0 + 2) = a3;
    }
}

__global__ void __launch_bounds__(256, 1) convlstm_kernel(
    const float* __restrict__ x,
    const float* __restrict__ W1, const float* __restrict__ b1,
    const float* __restrict__ W2, const float* __restrict__ b2,
    const float* __restrict__ W3, const float* __restrict__ b3,
    const float* __restrict__ h1i, const float* __restrict__ c1i,
    const float* __restrict__ h2i, const float* __restrict__ c2i,
    const float* __restrict__ h3i, const float* __restrict__ c3i,
    float* __restrict__ out)
{
    extern __shared__ float sm[];
    float* Wsm  = sm;
    float* zdf  = sm + ZD_OFF;
    float* gbuf = sm + GB_OFF;

    const int tid = threadIdx.x;
    const int gid = blockIdx.x & 7;    // gate-slice: hidden units [16*gid, +16)
    const int bg  = blockIdx.x >> 3;   // batch group: batches [16*bg, +16)
    const int bgb = bg << 4;

    // ---- Prologue: weight slices (center tap), [half(pad)][k][row64] ----
    for (int idx = tid; idx < 192 * 64; idx += 256) {
        int k = idx >> 6, r = idx & 63;
        int grow = ((r >> 4) << 7) | (gid << 4) | (r & 15);  // gate*128+gid*16+u
        int q = k / 96, kl = k % 96;
        Wsm[WOFF_L0 + q * 6160 + kl * 64 + r] = W1[(size_t)grow * 576 + k * 3 + 1];
    }
    for (int idx = tid; idx < 256 * 64; idx += 256) {
        int k = idx >> 6, r = idx & 63;
        int grow = ((r >> 4) << 7) | (gid << 4) | (r & 15);
        int q = k >> 7, kl = k & 127;
        Wsm[WOFF_L1 + q * 8208 + kl * 64 + r] = W2[(size_t)grow * 768 + k * 3 + 1];
        Wsm[WOFF_L2 + q * 8208 + kl * 64 + r] = W3[(size_t)grow * 768 + k * 3 + 1];
    }

    // ---- per-thread (u,b) registers: bias + c state ----
    const int u = tid >> 4, b = tid & 15;
    const int gub = (gid << 4) | u;
    float4 bL0 = make_float4(__ldg(&b1[gub]), __ldg(&b1[128 + gub]),
                             __ldg(&b1[256 + gub]), __ldg(&b1[384 + gub]));
    float4 bL1 = make_float4(__ldg(&b2[gub]), __ldg(&b2[128 + gub]),
                             __ldg(&b2[256 + gub]), __ldg(&b2[384 + gub]));
    float4 bL2 = make_float4(__ldg(&b3[gub]), __ldg(&b3[128 + gub]),
                             __ldg(&b3[256 + gub]), __ldg(&b3[384 + gub]));
    const int sidx = (bgb + b) * 128 + gub;
    float c0r = __ldg(&c1i[sidx]);
    float c1r = __ldg(&c2i[sidx]);
    float c2r = __ldg(&c3i[sidx]);

    // ---- publish initial h into both parities ----
    {
        float h0 = __ldg(&h1i[sidx]), h1v = __ldg(&h2i[sidx]), h2v = __ldg(&h3i[sidx]);
        int hb = gub * 256 + bgb + b;
#pragma unroll
        for (int par = 0; par < 2; par++) {
            g_hbuf[(0 * 2 + par) * 32768 + hb] = h0;
            g_hbuf[(1 * 2 + par) * 32768 + hb] = h1v;
            g_hbuf[(2 * 2 + par) * 32768 + hb] = h2v;
        }
    }
    unsigned target = 8;
    group_barrier(bg, target); target += 8;

    // GEMV warp/lane geometry: 8 warps = 4 rg x 2 bs; lane = kh x oct x pr
    // Coverage: 4rg x 2bs x 2kh x 4oct x 4pr = 256 = blockDim  (complete)
    const int warp = tid >> 5, lane = tid & 31;
    const int rg = warp & 3;             // 16-row group
    const int bs = warp >> 2;            // 8-batch half
    const int kh = lane >> 4;            // k-half (reduced in-lane via bfly16)
    const int oct = (lane >> 2) & 3;     // 4-row quad within group
    const int pr  = lane & 3;            // batch pair within half
    const int r0 = rg * 16 + oct * 4;    // row offset 0..60
    const int b0 = bs * 8 + pr * 2;      // even batch index

    // ======================= macro-step pipeline =======================
    for (int s = 0; s < T_STEPS + 2; s++) {
        const int pc = s & 1, pp = pc ^ 1;

        // ---- assemble z = [x(s) | h0 | h1 | h2] (448 rows x 16 b, stride 20) ----
        if (s < T_STEPS) {
            const float* xb = x + (size_t)bgb * (T_STEPS * 64) + (size_t)s * 64;
            int bb = tid >> 4, k4 = (tid & 15) << 2;
            float4 v = __ldg((const float4*)(xb + (size_t)bb * (T_STEPS * 64) + k4));
            zdf[(k4 + 0) * 20 + bb] = v.x;
            zdf[(k4 + 1) * 20 + bb] = v.y;
            zdf[(k4 + 2) * 20 + bb] = v.z;
            zdf[(k4 + 3) * 20 + bb] = v.w;
        }
#pragma unroll
        for (int Lh = 0; Lh < 3; Lh++) {
            const float* src = &g_hbuf[(Lh * 2 + pp) * 32768 + bgb];
#pragma unroll
            for (int i = 0; i < 2; i++) {
                int idx = tid + (i << 8);
                int unit = idx >> 2, b4 = (idx & 3) << 2;
                float4 v = __ldcg((const float4*)&src[unit * 256 + b4]);
                *(float4*)&zdf[(64 + (Lh << 7) + unit) * 20 + b4] = v;
            }
        }
        __syncthreads();

        // ---- all three GEMVs, sync-free stretch ----
        if (s < T_STEPS)
            gemv_layer<192>(Wsm + WOFF_L0, zdf,            kh, r0, b0, gbuf);
        if (s >= 1 && s <= T_STEPS)
            gemv_layer<256>(Wsm + WOFF_L1, zdf + 64 * 20,  kh, r0, b0, gbuf + 1056);
        if (s >= 2)
            gemv_layer<256>(Wsm + WOFF_L2, zdf + 192 * 20, kh, r0, b0, gbuf + 2112);
        __syncthreads();

        // ---- all three cells (one (u,b) per thread) ----
        if (s < T_STEPS) {
            const float* gb = gbuf + b * 66;
            float gi = gb[u] + bL0.x, gf = gb[16 + u] + bL0.y;
            float go = gb[32 + u] + bL0.z, gg = gb[48 + u] + bL0.w;
            float cn = sigm(gf) * c0r + sigm(gi) * tanh_f(gg);
            float hn = sigm(go) * tanh_f(cn);
            c0r = cn;
            g_hbuf[(0 * 2 + pc) * 32768 + gub * 256 + bgb + b] = hn;
        }
        if (s >= 1 && s <= T_STEPS) {
            const float* gb = gbuf + 1056 + b * 66;
            float gi = gb[u] + bL1.x, gf = gb[16 + u] + bL1.y;
            float go = gb[32 + u] + bL1.z, gg = gb[48 + u] + bL1.w;
            float cn = sigm(gf) * c1r + sigm(gi) * tanh_f(gg);
            float hn = sigm(go) * tanh_f(cn);
            c1r = cn;
            g_hbuf[(1 * 2 + pc) * 32768 + gub * 256 + bgb + b] = hn;
        }
        if (s >= 2) {
            const float* gb = gbuf + 2112 + b * 66;
            float gi = gb[u] + bL2.x, gf = gb[16 + u] + bL2.y;
            float go = gb[32 + u] + bL2.z, gg = gb[48 + u] + bL2.w;
            float cn = sigm(gf) * c2r + sigm(gi) * tanh_f(gg);
            float hn = sigm(go) * tanh_f(cn);
            c2r = cn;
            g_hbuf[(2 * 2 + pc) * 32768 + gub * 256 + bgb + b] = hn;
            if (s == T_STEPS + 1)
                out[(size_t)(bgb + b) * 128 + gub] = hn;
        }

        group_barrier(bg, target); target += 8;
    }
}

extern "C" void kernel_launch(void* const* d_in, const int* in_sizes, int n_in,
                              void* d_out, int out_size) {
    (void)in_sizes; (void)n_in; (void)out_size;
    const float* x  = (const float*)d_in[0];
    const float* W1 = (const float*)d_in[1];
    const float* b1 = (const float*)d_in[2];
    const float* W2 = (const float*)d_in[3];
    const float* b2 = (const float*)d_in[4];
    const float* W3 = (const float*)d_in[5];
    const float* b3 = (const float*)d_in[6];
    const float* h1 = (const float*)d_in[7];
    const float* c1 = (const float*)d_in[8];
    const float* h2 = (const float*)d_in[9];
    const float* c2 = (const float*)d_in[10];
    const float* h3 = (const float*)d_in[11];
    const float* c3 = (const float*)d_in[12];
    float* out = (float*)d_out;

    cudaFuncSetAttribute(convlstm_kernel,
                         cudaFuncAttributeMaxDynamicSharedMemorySize, SMEM_BYTES);
    reset_ctr_kernel<<<1, 32>>>();
    convlstm_kernel<<<128, 256, SMEM_BYTES>>>(x, W1, b1, W2, b2, W3, b3,
                                              h1, c1, h2, c2, h3, c3, out);
}

// round 10
// speedup vs baseline: 1.2003x; 1.0580x over previous
#include <cuda_runtime.h>
#include <cstdint>

// ============================================================================
// ConvLSTMEncoder == 3-layer LSTM (K=3 conv over length-1 dim -> center tap).
//   B=256, T=512, CIN=64, H=128.  gates[b,4H] = [in; h] @ Wc^T + bias
// Round-10: LDS-wavefront reduction. Evidence (R1/R4/R5/R8 all match a
// no-dedup shared-memory wavefront model) says the binder is smem crossbar
// traffic, 6 B per f32x2-FMA. This round: fat lane tile 8 rows x 4 batches
// (w 32B + z 16B per 16 FMA2 = 3 B/FMA2 -> halves LDS wavefronts).
//   Warps: kq(2) x rh(2: 32-row half) x bh(2: 8-batch half).
//   Lane:  ro(4: 8-row block) x bp(2: 4-batch) x kh(2) x k4(2).
//   k split 8 ways (kq warp-level x kh,k4 in-lane, folded via 2x shfl.bfly)
//   -> 2-copy partial buffer (kq), summed in the cell phase.
//   Layers sequential per macro (single pbuf): asm,BAR,(gemv,BAR,cell,BAR)x3,
//   then split cross-CTA barrier with x(s+1) assembly overlapping the poll.
// Also: barrier counters padded to one per 128B line (they shared ONE L2
// line = one LTS slice for all 128 CTAs' atomics+polls).
// 128 CTAs = 16 batch-groups x 8 gate-slices; weights fp32 in SMEM;
// h exchange via L2 __device__ buffer + monotonic counter barrier.
// ============================================================================

#define T_STEPS 512

// smem float offsets:
#define WOFF_L0 0            // 192*64 = 12288
#define WOFF_L1 12288        // 256*64 = 16384
#define WOFF_L2 28672        // 16384
#define ZD_OFF  45056        // z: [448][20] floats = 8960
#define PB_OFF  54016        // pbuf: [2][16][66] floats = 2112
#define SMEM_FLOATS 56128
#define SMEM_BYTES  (SMEM_FLOATS * 4)   // 224512

__device__ float    g_hbuf[3 * 2 * 128 * 256];  // [layer][parity][unit][batch]
__device__ unsigned g_ctr[16 * 32];             // padded: one counter / 128B

__global__ void reset_ctr_kernel() {
    if (threadIdx.x < 16) g_ctr[threadIdx.x * 32] = 0u;
}

__device__ __forceinline__ float fast_rcp(float x) {
    float r; asm("rcp.approx.f32 %0, %1;" : "=f"(r) : "f"(x)); return r;
}
__device__ __forceinline__ float sigm(float x) {
    return fast_rcp(1.0f + __expf(-x));
}
__device__ __forceinline__ float tanh_f(float x) {
    x = fminf(fmaxf(x, -15.0f), 15.0f);
    float e = __expf(-2.0f * x);
    return (1.0f - e) * fast_rcp(1.0f + e);
}

#define FMA2(acc, a, b) asm("fma.rn.f32x2 %0, %1, %2, %0;" : "+l"(acc) : "l"(a), "l"(b))
#define DUP2(d, s)      asm("mov.b64 %0, {%1, %1};" : "=l"(d) : "r"(__float_as_uint(s)))

// butterfly reduce of an f32x2 pair across lanes (xor mask)
__device__ __forceinline__ unsigned long long bfly_add2(unsigned long long a, int m) {
    unsigned lo = (unsigned)a, hi = (unsigned)(a >> 32);
    unsigned plo = __shfl_xor_sync(0xffffffffu, lo, m);
    unsigned phi = __shfl_xor_sync(0xffffffffu, hi, m);
    unsigned long long p = ((unsigned long long)phi << 32) | plo;
    unsigned long long r;
    asm("add.rn.f32x2 %0, %1, %2;" : "=l"(r) : "l"(a), "l"(p));
    return r;
}

// GEMV for one layer: lane tile 8 rows x 4 batches over its k-eighth.
// kh,k4 folded in-lane (bfly 8,16); kq==warp-level -> 2 pbuf copies.
template<int KD>
__device__ __forceinline__ void gemv_layer(
    const float* __restrict__ Wbase,   // Wsm + layer offset
    const float* __restrict__ zbase,   // zdf + zrow0*20
    int kq, int kl, int r0, int b0, int lane, float* __restrict__ pbuf)
{
    constexpr int C = KD / 8;          // iters per lane
    const int kc = kq * 4 + kl;        // k-chunk 0..7
    const float* Wcol = Wbase + kc * (C * 64) + r0;
    const float* zcol = zbase + kc * (C * 20) + b0;

    unsigned long long acc[4][4];
#pragma unroll
    for (int i = 0; i < 4; i++)
#pragma unroll
        for (int j = 0; j < 4; j++) acc[i][j] = 0ULL;

#pragma unroll 4
    for (int k = 0; k < C; k++) {
        ulonglong2 wa = *(const ulonglong2*)(Wcol + k * 64);      // rows r0..r0+3
        ulonglong2 wb = *(const ulonglong2*)(Wcol + k * 64 + 4);  // rows r0+4..r0+7
        float4 z4 = *(const float4*)(zcol + k * 20);              // batches b0..b0+3
        unsigned long long zz[4];
        DUP2(zz[0], z4.x); DUP2(zz[1], z4.y);
        DUP2(zz[2], z4.z); DUP2(zz[3], z4.w);
#pragma unroll
        for (int j = 0; j < 4; j++) {
            FMA2(acc[0][j], wa.x, zz[j]);
            FMA2(acc[1][j], wa.y, zz[j]);
            FMA2(acc[2][j], wb.x, zz[j]);
            FMA2(acc[3][j], wb.y, zz[j]);
        }
    }
    // fold kh (bfly 8) and k4 (bfly 16)
#pragma unroll
    for (int i = 0; i < 4; i++)
#pragma unroll
        for (int j = 0; j < 4; j++)
            acc[i][j] = bfly_add2(bfly_add2(acc[i][j], 8), 16);

    if (lane < 8) {   // kh==0 && k4==0
        float* pd = pbuf + kq * 1056;
#pragma unroll
        for (int j = 0; j < 4; j++) {
            float* col = pd + (b0 + j) * 66 + r0;
#pragma unroll
            for (int i = 0; i < 4; i++)
                *(unsigned long long*)(col + 2 * i) = acc[i][j];
        }
    }
}

__global__ void __launch_bounds__(256, 1) convlstm_kernel(
    const float* __restrict__ x,
    const float* __restrict__ W1, const float* __restrict__ b1,
    const float* __restrict__ W2, const float* __restrict__ b2,
    const float* __restrict__ W3, const float* __restrict__ b3,
    const float* __restrict__ h1i, const float* __restrict__ c1i,
    const float* __restrict__ h2i, const float* __restrict__ c2i,
    const float* __restrict__ h3i, const float* __restrict__ c3i,
    float* __restrict__ out)
{
    extern __shared__ float sm[];
    float* Wsm  = sm;
    float* zdf  = sm + ZD_OFF;
    float* pbuf = sm + PB_OFF;

    const int tid = threadIdx.x;
    const int gid = blockIdx.x & 7;    // gate-slice: hidden units [16*gid, +16)
    const int bg  = blockIdx.x >> 3;   // batch group: batches [16*bg, +16)
    const int bgb = bg << 4;
    unsigned* ctr = &g_ctr[bg * 32];

    // ---- Prologue: weight slices (center tap), plain [k][row64] ----
    for (int idx = tid; idx < 192 * 64; idx += 256) {
        int k = idx >> 6, r = idx & 63;
        int grow = ((r >> 4) << 7) | (gid << 4) | (r & 15);  // gate*128+gid*16+u
        Wsm[WOFF_L0 + idx] = W1[(size_t)grow * 576 + k * 3 + 1];
    }
    for (int idx = tid; idx < 256 * 64; idx += 256) {
        int k = idx >> 6, r = idx & 63;
        int grow = ((r >> 4) << 7) | (gid << 4) | (r & 15);
        Wsm[WOFF_L1 + idx] = W2[(size_t)grow * 768 + k * 3 + 1];
        Wsm[WOFF_L2 + idx] = W3[(size_t)grow * 768 + k * 3 + 1];
    }

    // ---- per-thread (u,b) registers: bias + c state ----
    const int u = tid >> 4, b = tid & 15;
    const int gub = (gid << 4) | u;
    float4 bL0 = make_float4(__ldg(&b1[gub]), __ldg(&b1[128 + gub]),
                             __ldg(&b1[256 + gub]), __ldg(&b1[384 + gub]));
    float4 bL1 = make_float4(__ldg(&b2[gub]), __ldg(&b2[128 + gub]),
                             __ldg(&b2[256 + gub]), __ldg(&b2[384 + gub]));
    float4 bL2 = make_float4(__ldg(&b3[gub]), __ldg(&b3[128 + gub]),
                             __ldg(&b3[256 + gub]), __ldg(&b3[384 + gub]));
    const int sidx = (bgb + b) * 128 + gub;
    float c0r = __ldg(&c1i[sidx]);
    float c1r = __ldg(&c2i[sidx]);
    float c2r = __ldg(&c3i[sidx]);

    // ---- publish initial h into both parities ----
    {
        float h0 = __ldg(&h1i[sidx]), h1v = __ldg(&h2i[sidx]), h2v = __ldg(&h3i[sidx]);
        int hb = gub * 256 + bgb + b;
#pragma unroll
        for (int par = 0; par < 2; par++) {
            g_hbuf[(0 * 2 + par) * 32768 + hb] = h0;
            g_hbuf[(1 * 2 + par) * 32768 + hb] = h1v;
            g_hbuf[(2 * 2 + par) * 32768 + hb] = h2v;
        }
    }
    // initial cross-CTA barrier
    unsigned target = 8;
    __syncthreads();
    if (tid == 0) {
        __threadfence();
        atomicAdd(ctr, 1u);
        unsigned v;
        do {
            asm volatile("ld.global.acquire.gpu.u32 %0, [%1];"
                         : "=r"(v) : "l"(ctr) : "memory");
            if (v < target) __nanosleep(20);
        } while (v < target);
    }
    target += 8;
    __syncthreads();

    // ---- initial x(0) assembly ----
    {
        const float* xb = x + (size_t)bgb * (T_STEPS * 64);
        int bb = tid >> 4, k4i = (tid & 15) << 2;
        float4 v = __ldg((const float4*)(xb + (size_t)bb * (T_STEPS * 64) + k4i));
        zdf[(k4i + 0) * 20 + bb] = v.x;
        zdf[(k4i + 1) * 20 + bb] = v.y;
        zdf[(k4i + 2) * 20 + bb] = v.z;
        zdf[(k4i + 3) * 20 + bb] = v.w;
    }

    // GEMV warp/lane geometry
    const int warp = tid >> 5, lane = tid & 31;
    const int kq = warp & 1;             // k-half (pbuf copy)
    const int rh = (warp >> 1) & 1;      // 32-row half
    const int bh = warp >> 2;            // 8-batch half
    const int ro = lane & 3;             // 8-row block within half
    const int bp = (lane >> 2) & 1;      // 4-batch within half
    const int kl = lane >> 3;            // in-lane k-chunk (kh*2+k4), folded
    const int r0 = rh * 32 + ro * 8;     // rows r0..r0+7
    const int b0 = bh * 8 + bp * 4;      // batches b0..b0+3

    // ======================= macro-step pipeline =======================
    for (int s = 0; s < T_STEPS + 2; s++) {
        const int pc = s & 1, pp = pc ^ 1;

        // ---- h-assembly: z rows 64..447 (x already written last macro) ----
#pragma unroll
        for (int Lh = 0; Lh < 3; Lh++) {
            const float* src = &g_hbuf[(Lh * 2 + pp) * 32768 + bgb];
#pragma unroll
            for (int i = 0; i < 2; i++) {
                int idx = tid + (i << 8);
                int unit = idx >> 2, b4 = (idx & 3) << 2;
                float4 v = __ldcg((const float4*)&src[unit * 256 + b4]);
                *(float4*)&zdf[(64 + (Lh << 7) + unit) * 20 + b4] = v;
            }
        }
        __syncthreads();

        // -------- L0: t = s  (z rows 0..191) --------
        if (s < T_STEPS)
            gemv_layer<192>(Wsm + WOFF_L0, zdf, kq, kl, r0, b0, lane, pbuf);
        __syncthreads();
        if (s < T_STEPS) {
            const float* gb = pbuf + b * 66;
            float gi = gb[u] + gb[1056 + u] + bL0.x;
            float gf = gb[16 + u] + gb[1056 + 16 + u] + bL0.y;
            float go = gb[32 + u] + gb[1056 + 32 + u] + bL0.z;
            float gg = gb[48 + u] + gb[1056 + 48 + u] + bL0.w;
            float cn = sigm(gf) * c0r + sigm(gi) * tanh_f(gg);
            float hn = sigm(go) * tanh_f(cn);
            c0r = cn;
            g_hbuf[(0 * 2 + pc) * 32768 + gub * 256 + bgb + b] = hn;
        }
        __syncthreads();

        // -------- L1: t = s-1  (z rows 64..319) --------
        if (s >= 1 && s <= T_STEPS)
            gemv_layer<256>(Wsm + WOFF_L1, zdf + 64 * 20, kq, kl, r0, b0, lane, pbuf);
        __syncthreads();
        if (s >= 1 && s <= T_STEPS) {
            const float* gb = pbuf + b * 66;
            float gi = gb[u] + gb[1056 + u] + bL1.x;
            float gf = gb[16 + u] + gb[1056 + 16 + u] + bL1.y;
            float go = gb[32 + u] + gb[1056 + 32 + u] + bL1.z;
            float gg = gb[48 + u] + gb[1056 + 48 + u] + bL1.w;
            float cn = sigm(gf) * c1r + sigm(gi) * tanh_f(gg);
            float hn = sigm(go) * tanh_f(cn);
            c1r = cn;
            g_hbuf[(1 * 2 + pc) * 32768 + gub * 256 + bgb + b] = hn;
        }
        __syncthreads();

        // -------- L2: t = s-2  (z rows 192..447) --------
        if (s >= 2)
            gemv_layer<256>(Wsm + WOFF_L2, zdf + 192 * 20, kq, kl, r0, b0, lane, pbuf);
        __syncthreads();
        if (s >= 2) {
            const float* gb = pbuf + b * 66;
            float gi = gb[u] + gb[1056 + u] + bL2.x;
            float gf = gb[16 + u] + gb[1056 + 16 + u] + bL2.y;
            float go = gb[32 + u] + gb[1056 + 32 + u] + bL2.z;
            float gg = gb[48 + u] + gb[1056 + 48 + u] + bL2.w;
            float cn = sigm(gf) * c2r + sigm(gi) * tanh_f(gg);
            float hn = sigm(go) * tanh_f(cn);
            c2r = cn;
            g_hbuf[(2 * 2 + pc) * 32768 + gub * 256 + bgb + b] = hn;
            if (s == T_STEPS + 1)
                out[(size_t)(bgb + b) * 128 + gub] = hn;
        }

        // ---- split cross-CTA barrier; x(s+1) assembly overlaps the poll ----
        __syncthreads();
        if (tid == 0) {
            __threadfence();
            atomicAdd(ctr, 1u);
        }
        if (s + 1 < T_STEPS) {
            const float* xb = x + (size_t)bgb * (T_STEPS * 64) + (size_t)(s + 1) * 64;
            int bb = tid >> 4, k4i = (tid & 15) << 2;
            float4 v = __ldg((const float4*)(xb + (size_t)bb * (T_STEPS * 64) + k4i));
            zdf[(k4i + 0) * 20 + bb] = v.x;
            zdf[(k4i + 1) * 20 + bb] = v.y;
            zdf[(k4i + 2) * 20 + bb] = v.z;
            zdf[(k4i + 3) * 20 + bb] = v.w;
        }
        if (tid == 0) {
            unsigned v;
            do {
                asm volatile("ld.global.acquire.gpu.u32 %0, [%1];"
                             : "=r"(v) : "l"(ctr) : "memory");
                if (v < target) __nanosleep(20);
            } while (v < target);
        }
        target += 8;
        __syncthreads();
    }
}

extern "C" void kernel_launch(void* const* d_in, const int* in_sizes, int n_in,
                              void* d_out, int out_size) {
    (void)in_sizes; (void)n_in; (void)out_size;
    const float* x  = (const float*)d_in[0];
    const float* W1 = (const float*)d_in[1];
    const float* b1 = (const float*)d_in[2];
    const float* W2 = (const float*)d_in[3];
    const float* b2 = (const float*)d_in[4];
    const float* W3 = (const float*)d_in[5];
    const float* b3 = (const float*)d_in[6];
    const float* h1 = (const float*)d_in[7];
    const float* c1 = (const float*)d_in[8];
    const float* h2 = (const float*)d_in[9];
    const float* c2 = (const float*)d_in[10];
    const float* h3 = (const float*)d_in[11];
    const float* c3 = (const float*)d_in[12];
    float* out = (float*)d_out;

    cudaFuncSetAttribute(convlstm_kernel,
                         cudaFuncAttributeMaxDynamicSharedMemorySize, SMEM_BYTES);
    reset_ctr_kernel<<<1, 32>>>();
    convlstm_kernel<<<128, 256, SMEM_BYTES>>>(x, W1, b1, W2, b2, W3, b3,
                                              h1, c1, h2, c2, h3, c3, out);
}